// round 14
// baseline (speedup 1.0000x reference)
#include <cuda_runtime.h>
#include <stdint.h>
#include <math.h>

#define NTOK 16384
#define HD   4096
#define NE   64
#define NP   6
#define TK   8

#define NTHREADS 128
#define GRID     (148 * 8)          // 8 CTAs/SM, persistent via counter

__device__ unsigned g_tok_ctr;

#define FMA2(acc, a, b) \
    asm("fma.rn.f32x2 %0, %1, %2, %0;" : "+l"(acc) : "l"(a), "l"(b))
#define ADD2(d, a, b) \
    asm("add.rn.f32x2 %0, %1, %2;" : "=l"(d) : "l"(a), "l"(b))

__global__ void reset_ctr_kernel() { g_tok_ctr = 0u; }

__global__ void __launch_bounds__(NTHREADS, 8)
kdtree_router_kernel(const float* __restrict__ x,
                     const float* __restrict__ mean,
                     const float* __restrict__ comp,
                     const float* __restrict__ cent,
                     float* __restrict__ out)
{
    __shared__ float cent_s[NE * NP];
    __shared__ float centn_s[NE];

    const int tid  = threadIdx.x;
    const int lane = tid & 31;

    for (int i = tid; i < NE * NP; i += NTHREADS) cent_s[i] = cent[i];
    __syncthreads();
    if (tid < NE) {
        float s = 0.f;
        #pragma unroll
        for (int p = 0; p < NP; p++) { float c = cent_s[tid*NP + p]; s += c * c; }
        centn_s[tid] = s;
    }
    __syncthreads();

    const ulonglong2* compU = (const ulonglong2*)comp;   // NP rows x 1024 ull2

    // ---- per-warp mean projection (warp-local, columns lane*2 .. +1 per iter) ----
    float mpj[NP];
    {
        const ulonglong2* mU = (const ulonglong2*)mean;
        unsigned long long acc[NP];
        #pragma unroll
        for (int p = 0; p < NP; p++) acc[p] = 0ull;
        #pragma unroll 2
        for (int i = 0; i < 16; i++) {
            int idx = i * 64 + lane * 2;
            ulonglong2 a = __ldg(mU + idx);
            ulonglong2 b = __ldg(mU + idx + 1);
            #pragma unroll
            for (int p = 0; p < NP; p++) {
                ulonglong2 c0 = __ldg(compU + p * 1024 + idx);
                ulonglong2 c1 = __ldg(compU + p * 1024 + idx + 1);
                FMA2(acc[p], a.x, c0.x); FMA2(acc[p], a.y, c0.y);
                FMA2(acc[p], b.x, c1.x); FMA2(acc[p], b.y, c1.y);
            }
        }
        unsigned long long u[3];
        #pragma unroll
        for (int j = 0; j < 3; j++) {
            float f0 = __uint_as_float((unsigned)(acc[2*j]   & 0xffffffffull)) +
                       __uint_as_float((unsigned)(acc[2*j]   >> 32));
            float f1 = __uint_as_float((unsigned)(acc[2*j+1] & 0xffffffffull)) +
                       __uint_as_float((unsigned)(acc[2*j+1] >> 32));
            u[j] = ((unsigned long long)__float_as_uint(f1) << 32) | __float_as_uint(f0);
        }
        #pragma unroll
        for (int o = 16; o >= 1; o >>= 1)
            #pragma unroll
            for (int j = 0; j < 3; j++) {
                unsigned long long v = __shfl_xor_sync(0xffffffffu, u[j], o);
                ADD2(u[j], u[j], v);
            }
        #pragma unroll
        for (int j = 0; j < 3; j++) {
            mpj[2*j]   = __uint_as_float((unsigned)(u[j] & 0xffffffffull));
            mpj[2*j+1] = __uint_as_float((unsigned)(u[j] >> 32));
        }
    }

    float* out_idx = out;
    float* out_tp  = out + (size_t)NTOK * TK;
    float* out_pr  = out + 2 * (size_t)NTOK * TK;

    // ================= autonomous per-warp token loop (no barriers) =================
    for (;;) {
        unsigned tok;
        if (lane == 0) tok = atomicAdd(&g_tok_ctr, 1u);
        tok = __shfl_sync(0xffffffffu, tok, 0);
        if (tok >= NTOK) break;

        const ulonglong2* xU = (const ulonglong2*)(x + (size_t)tok * HD);
        unsigned long long acc[NP];
        #pragma unroll
        for (int p = 0; p < NP; p++) acc[p] = 0ull;

        #pragma unroll 2
        for (int i = 0; i < 16; i++) {
            int idx = i * 64 + lane * 2;
            ulonglong2 a = __ldcs(xU + idx);
            ulonglong2 b = __ldcs(xU + idx + 1);
            #pragma unroll
            for (int p = 0; p < NP; p++) {
                ulonglong2 c0 = __ldg(compU + p * 1024 + idx);
                ulonglong2 c1 = __ldg(compU + p * 1024 + idx + 1);
                FMA2(acc[p], a.x, c0.x); FMA2(acc[p], a.y, c0.y);
                FMA2(acc[p], b.x, c1.x); FMA2(acc[p], b.y, c1.y);
            }
        }

        // ---- warp-local reduce -> pr[6] in all lanes ----
        float pr[NP];
        {
            unsigned long long u[3];
            #pragma unroll
            for (int j = 0; j < 3; j++) {
                float f0 = __uint_as_float((unsigned)(acc[2*j]   & 0xffffffffull)) +
                           __uint_as_float((unsigned)(acc[2*j]   >> 32));
                float f1 = __uint_as_float((unsigned)(acc[2*j+1] & 0xffffffffull)) +
                           __uint_as_float((unsigned)(acc[2*j+1] >> 32));
                u[j] = ((unsigned long long)__float_as_uint(f1) << 32) | __float_as_uint(f0);
            }
            #pragma unroll
            for (int o = 16; o >= 1; o >>= 1)
                #pragma unroll
                for (int j = 0; j < 3; j++) {
                    unsigned long long v = __shfl_xor_sync(0xffffffffu, u[j], o);
                    ADD2(u[j], u[j], v);
                }
            #pragma unroll
            for (int j = 0; j < 3; j++) {
                pr[2*j]   = __uint_as_float((unsigned)(u[j] & 0xffffffffull)) - mpj[2*j];
                pr[2*j+1] = __uint_as_float((unsigned)(u[j] >> 32))           - mpj[2*j+1];
            }
        }

        // ---- warp-local epilogue: distances, softmax(64), top-8 ----
        float pn = 0.f;
        #pragma unroll
        for (int p = 0; p < NP; p++) pn += pr[p] * pr[p];

        const int e0 = lane, e1 = lane + 32;
        float dot0 = 0.f, dot1 = 0.f;
        #pragma unroll
        for (int p = 0; p < NP; p++) {
            dot0 += pr[p] * cent_s[e0*NP + p];
            dot1 += pr[p] * cent_s[e1*NP + p];
        }
        float d20 = pn - 2.f*dot0 + centn_s[e0];
        float d21 = pn - 2.f*dot1 + centn_s[e1];
        float s0 = -sqrtf(fmaxf(d20, 0.f));
        float s1 = -sqrtf(fmaxf(d21, 0.f));

        float m = fmaxf(s0, s1);
        #pragma unroll
        for (int o = 16; o > 0; o >>= 1)
            m = fmaxf(m, __shfl_xor_sync(0xffffffffu, m, o));
        float ex0 = expf(s0 - m);
        float ex1 = expf(s1 - m);
        float sum = ex0 + ex1;
        #pragma unroll
        for (int o = 16; o > 0; o >>= 1)
            sum += __shfl_xor_sync(0xffffffffu, sum, o);
        float p0 = ex0 / sum;
        float p1 = ex1 / sum;

        out_pr[(size_t)tok*NE + e0] = p0;
        out_pr[(size_t)tok*NE + e1] = p1;

        // top-8 via 8-round warp argmax; tie-break = lower index (jax.lax.top_k)
        unsigned long long k0 = ((unsigned long long)__float_as_uint(p0) << 32) | (unsigned)(NE-1 - e0);
        unsigned long long k1 = ((unsigned long long)__float_as_uint(p1) << 32) | (unsigned)(NE-1 - e1);
        float tsum = 0.f, myp = 0.f;
        int myi = 0;
        #pragma unroll
        for (int r = 0; r < TK; r++) {
            unsigned long long b = (k0 > k1) ? k0 : k1;
            #pragma unroll
            for (int o = 16; o > 0; o >>= 1) {
                unsigned long long v = __shfl_xor_sync(0xffffffffu, b, o);
                if (v > b) b = v;
            }
            int idx = NE-1 - (int)(b & 0xffull);
            float pv = __uint_as_float((unsigned)(b >> 32));
            tsum += pv;
            if (lane == r) { myp = pv; myi = idx; }
            if (idx == e0) k0 = 0ull;
            if (idx == e1) k1 = 0ull;
        }
        if (lane < TK) {
            out_idx[(size_t)tok*TK + lane] = (float)myi;
            out_tp [(size_t)tok*TK + lane] = myp / tsum;
        }
    }
}

extern "C" void kernel_launch(void* const* d_in, const int* in_sizes, int n_in,
                              void* d_out, int out_size)
{
    const float* x    = (const float*)d_in[0];
    const float* mean = (const float*)d_in[1];
    const float* comp = (const float*)d_in[2];
    const float* cent = (const float*)d_in[3];
    float* out = (float*)d_out;

    reset_ctr_kernel<<<1, 1>>>();
    kdtree_router_kernel<<<GRID, NTHREADS>>>(x, mean, comp, cent, out);
}

// round 15
// speedup vs baseline: 1.7992x; 1.7992x over previous
#include <cuda_runtime.h>
#include <stdint.h>
#include <math.h>

#define NTOK 16384
#define HD   4096
#define NE   64
#define NP   6
#define TK   8

#define CWARPS   16
#define LWARPS   4
#define NTHREADS 672                 // 16 consumers + 1 producer + 4 LDG = 21 warps
#define PROD_WARP 16
#define SLICE    (HD / CWARPS)       // 256

#define NGROUP   (NTOK / 2)          // 8192 two-token groups
#define UNIT_TOK 16
#define STAGE_TOK 2
#define STAGE_BYTES (STAGE_TOK * HD * 4)   // 32768
#define NSPLIT    4
#define SPLIT_BYTES (STAGE_BYTES / NSPLIT)
#define STAGES    3
#define GRID      148

// smem byte offsets
#define XS_OFF    0
#define CS_OFF    (STAGES * STAGE_BYTES)                 // 98304: comp copy 96 KB
#define PART_OFF  (CS_OFF + NP * HD * 4)                 // 196608
#define PART_SZ   ((UNIT_TOK + 1) * NP * 32 * 4)         // 13056
#define CENT_OFF  (PART_OFF + PART_SZ)
#define CENTN_OFF (CENT_OFF + NE * NP * 4)
#define MPJ_OFF   (CENTN_OFF + NE * 4)
#define UID_OFF   (MPJ_OFF + 32)
#define MBAR_OFF  ((UID_OFF + 16 + 7) & ~7)
#define SMEM_BYTES (MBAR_OFF + 64)                        // ~211.6 KB

__device__ unsigned g_grp_ctr;

#define FMA2(acc, a, b) \
    asm("fma.rn.f32x2 %0, %1, %2, %0;" : "+l"(acc) : "l"(a), "l"(b))
#define ADD2(d, a, b) \
    asm("add.rn.f32x2 %0, %1, %2;" : "=l"(d) : "l"(a), "l"(b))

__device__ __forceinline__ uint32_t smem_u32(const void* p) {
    uint32_t a;
    asm("{ .reg .u64 t; cvta.to.shared.u64 t, %1; cvt.u32.u64 %0, t; }" : "=r"(a) : "l"(p));
    return a;
}

#define MBAR_INIT(addr, cnt) \
    asm volatile("mbarrier.init.shared.b64 [%0], %1;" :: "r"(addr), "r"(cnt) : "memory")
#define MBAR_EXPECT_TX(addr, bytes) \
    asm volatile("mbarrier.arrive.expect_tx.shared.b64 _, [%0], %1;" :: "r"(addr), "r"(bytes) : "memory")
#define MBAR_ARRIVE(addr) \
    asm volatile("mbarrier.arrive.shared.b64 _, [%0];" :: "r"(addr) : "memory")
#define MBAR_WAIT(addr, parity) do {                                             \
    asm volatile("{\n\t.reg .pred P;\n"                                          \
        "W_%=:\n\tmbarrier.try_wait.parity.acquire.cta.shared::cta.b64 P, [%0], %1, 0x989680;\n" \
        "\t@P bra D_%=;\n\tbra W_%=;\nD_%=:\n\t}"                                \
        :: "r"(addr), "r"(parity) : "memory"); } while (0)

__device__ __forceinline__ void bulk_g2s(uint32_t dst, const void* src,
                                         uint32_t bytes, uint32_t mbar) {
    asm volatile(
        "cp.async.bulk.shared::cta.global.mbarrier::complete_tx::bytes "
        "[%0], [%1], %2, [%3];"
        :: "r"(dst), "l"(src), "r"(bytes), "r"(mbar) : "memory");
}

#define CBAR() asm volatile("bar.sync 1, 512;" ::: "memory")

// consumer-slice partial: uses cA,cB,part,warp,lane from scope
#define TOKEN_COMPUTE(xa, xb, LTOK) do {                                              \
    unsigned long long acc_[NP];                                                      \
    _Pragma("unroll")                                                                 \
    for (int p_ = 0; p_ < NP; p_++) {                                                 \
        acc_[p_] = 0ull;                                                              \
        FMA2(acc_[p_], (xa).x, cA[p_].x); FMA2(acc_[p_], (xa).y, cA[p_].y);           \
        FMA2(acc_[p_], (xb).x, cB[p_].x); FMA2(acc_[p_], (xb).y, cB[p_].y);           \
    }                                                                                 \
    unsigned long long u_[3];                                                         \
    _Pragma("unroll")                                                                 \
    for (int j_ = 0; j_ < 3; j_++) {                                                  \
        float f0_ = __uint_as_float((unsigned)(acc_[2*j_]   & 0xffffffffull)) +       \
                    __uint_as_float((unsigned)(acc_[2*j_]   >> 32));                  \
        float f1_ = __uint_as_float((unsigned)(acc_[2*j_+1] & 0xffffffffull)) +       \
                    __uint_as_float((unsigned)(acc_[2*j_+1] >> 32));                  \
        u_[j_] = ((unsigned long long)__float_as_uint(f1_) << 32) | __float_as_uint(f0_); \
    }                                                                                 \
    _Pragma("unroll")                                                                 \
    for (int o_ = 16; o_ >= 2; o_ >>= 1)                                              \
        _Pragma("unroll")                                                             \
        for (int j_ = 0; j_ < 3; j_++) {                                              \
            unsigned long long v_ = __shfl_xor_sync(0xffffffffu, u_[j_], o_);         \
            ADD2(u_[j_], u_[j_], v_);                                                 \
        }                                                                             \
    if (lane < 2) {                                                                   \
        int slot_ = warp * 2 + lane;                                                  \
        _Pragma("unroll")                                                             \
        for (int j_ = 0; j_ < 3; j_++) {                                              \
            part[((LTOK)*NP + 2*j_  )*32 + slot_] = __uint_as_float((unsigned)(u_[j_] & 0xffffffffull)); \
            part[((LTOK)*NP + 2*j_+1)*32 + slot_] = __uint_as_float((unsigned)(u_[j_] >> 32));           \
        }                                                                             \
    }                                                                                 \
} while (0)

// warp-local epilogue for token TOK given pr[6] in all lanes
#define WARP_EPILOGUE(TOK, pr) do {                                                   \
    float pn_ = 0.f;                                                                  \
    _Pragma("unroll")                                                                 \
    for (int p_ = 0; p_ < NP; p_++) pn_ += (pr)[p_] * (pr)[p_];                       \
    const int e0_ = lane, e1_ = lane + 32;                                            \
    float dot0_ = 0.f, dot1_ = 0.f;                                                   \
    _Pragma("unroll")                                                                 \
    for (int p_ = 0; p_ < NP; p_++) {                                                 \
        dot0_ += (pr)[p_] * cent_s[e0_*NP + p_];                                      \
        dot1_ += (pr)[p_] * cent_s[e1_*NP + p_];                                      \
    }                                                                                 \
    float s0_ = -sqrtf(fmaxf(pn_ - 2.f*dot0_ + centn_s[e0_], 0.f));                   \
    float s1_ = -sqrtf(fmaxf(pn_ - 2.f*dot1_ + centn_s[e1_], 0.f));                   \
    float m_ = fmaxf(s0_, s1_);                                                       \
    _Pragma("unroll")                                                                 \
    for (int o_ = 16; o_ > 0; o_ >>= 1)                                               \
        m_ = fmaxf(m_, __shfl_xor_sync(0xffffffffu, m_, o_));                         \
    float ex0_ = expf(s0_ - m_), ex1_ = expf(s1_ - m_);                               \
    float sm_ = ex0_ + ex1_;                                                          \
    _Pragma("unroll")                                                                 \
    for (int o_ = 16; o_ > 0; o_ >>= 1)                                               \
        sm_ += __shfl_xor_sync(0xffffffffu, sm_, o_);                                 \
    float p0_ = ex0_ / sm_, p1_ = ex1_ / sm_;                                         \
    out_pr[(size_t)(TOK)*NE + e0_] = p0_;                                             \
    out_pr[(size_t)(TOK)*NE + e1_] = p1_;                                             \
    unsigned long long k0_ = ((unsigned long long)__float_as_uint(p0_) << 32) | (unsigned)(NE-1 - e0_); \
    unsigned long long k1_ = ((unsigned long long)__float_as_uint(p1_) << 32) | (unsigned)(NE-1 - e1_); \
    float tsum_ = 0.f, myp_ = 0.f;                                                    \
    int myi_ = 0;                                                                     \
    _Pragma("unroll")                                                                 \
    for (int r_ = 0; r_ < TK; r_++) {                                                 \
        unsigned long long b_ = (k0_ > k1_) ? k0_ : k1_;                              \
        _Pragma("unroll")                                                             \
        for (int o_ = 16; o_ > 0; o_ >>= 1) {                                         \
            unsigned long long v_ = __shfl_xor_sync(0xffffffffu, b_, o_);             \
            if (v_ > b_) b_ = v_;                                                     \
        }                                                                             \
        int idx_ = NE-1 - (int)(b_ & 0xffull);                                        \
        float pv_ = __uint_as_float((unsigned)(b_ >> 32));                            \
        tsum_ += pv_;                                                                 \
        if (lane == r_) { myp_ = pv_; myi_ = idx_; }                                  \
        if (idx_ == e0_) k0_ = 0ull;                                                  \
        if (idx_ == e1_) k1_ = 0ull;                                                  \
    }                                                                                 \
    if (lane < TK) {                                                                  \
        out_idx[(size_t)(TOK)*TK + lane] = (float)myi_;                               \
        out_tp [(size_t)(TOK)*TK + lane] = myp_ / tsum_;                              \
    }                                                                                 \
} while (0)

__global__ void reset_ctr_kernel() { g_grp_ctr = 0u; }

__global__ void __launch_bounds__(NTHREADS, 1)
kdtree_router_kernel(const float* __restrict__ x,
                     const float* __restrict__ mean,
                     const float* __restrict__ comp,
                     const float* __restrict__ cent,
                     float* __restrict__ out)
{
    extern __shared__ __align__(1024) char smem_c[];
    float* comp_s  = (float*)(smem_c + CS_OFF);
    float* part    = (float*)(smem_c + PART_OFF);
    float* cent_s  = (float*)(smem_c + CENT_OFF);
    float* centn_s = (float*)(smem_c + CENTN_OFF);
    float* mpj_s   = (float*)(smem_c + MPJ_OFF);
    unsigned* uid  = (unsigned*)(smem_c + UID_OFF);
    const uint32_t mb = smem_u32(smem_c + MBAR_OFF);
    const uint32_t xs = smem_u32(smem_c + XS_OFF);

    const int tid  = threadIdx.x;
    const int lane = tid & 31;
    const int warp = tid >> 5;

    if (tid == 0) {
        #pragma unroll
        for (int s = 0; s < STAGES; s++) {
            MBAR_INIT(mb + s * 8, 1);               // full
            MBAR_INIT(mb + 24 + s * 8, CWARPS);     // empty
        }
    }
    // fill comp copy + centroids (all warps)
    {
        const float4* cg = (const float4*)comp;
        float4* cs = (float4*)comp_s;
        for (int i = tid; i < NP * HD / 4; i += NTHREADS) cs[i] = cg[i];
        for (int i = tid; i < NE * NP; i += NTHREADS) cent_s[i] = cent[i];
    }
    __syncthreads();

    // consumers: comp slice -> regs, mean partials -> part row 16
    ulonglong2 cA[NP], cB[NP];
    if (warp < CWARPS) {
        const ulonglong2* cp0 = (const ulonglong2*)(comp + warp * SLICE);
        #pragma unroll
        for (int p = 0; p < NP; p++) {
            cA[p] = cp0[(size_t)p * (HD/4) + lane];
            cB[p] = cp0[(size_t)p * (HD/4) + lane + 32];
        }
        const ulonglong2* mp = (const ulonglong2*)(mean + warp * SLICE);
        ulonglong2 ma = mp[lane], mbv = mp[lane + 32];
        TOKEN_COMPUTE(ma, mbv, UNIT_TOK);
    }
    if (tid < NE) {
        float s = 0.f;
        #pragma unroll
        for (int p = 0; p < NP; p++) { float c = cent_s[tid*NP + p]; s += c * c; }
        centn_s[tid] = s;
    }
    __syncthreads();
    if (tid < NP) {
        float s = 0.f;
        #pragma unroll
        for (int w = 0; w < 32; w++) s += part[(UNIT_TOK*NP + tid)*32 + w];
        mpj_s[tid] = s;
    }
    __syncthreads();

    float mpj[NP];
    #pragma unroll
    for (int p = 0; p < NP; p++) mpj[p] = mpj_s[p];

    float* out_idx = out;
    float* out_tp  = out + (size_t)NTOK * TK;
    float* out_pr  = out + 2 * (size_t)NTOK * TK;

    if (warp == PROD_WARP) {
        // ============ producer: claims 8 groups (16 tokens) at a time ============
        int s = 0, f = 0;
        for (;;) {
            unsigned g0;
            if (lane == 0) g0 = atomicAdd(&g_grp_ctr, 8u);
            g0 = __shfl_sync(0xffffffffu, g0, 0);
            if (g0 >= NGROUP) break;
            const int vg = min(8, (int)(NGROUP - g0));      // valid chunks this unit
            const unsigned tok0 = g0 * 2;
            #pragma unroll 1
            for (int ci = 0; ci < vg; ci++) {
                if (lane < NSPLIT && f >= 1)
                    MBAR_WAIT(mb + 24 + s * 8, (f & 1) ^ 1);
                __syncwarp();
                if (lane == 0) {
                    uid[s] = ((tok0 + ci*2) << 8) | ((unsigned)(ci*2) << 1)
                           | (ci == vg - 1 ? 1u : 0u);
                    MBAR_EXPECT_TX(mb + s * 8, (uint32_t)STAGE_BYTES);
                }
                __syncwarp();
                if (lane < NSPLIT)
                    bulk_g2s(xs + s * STAGE_BYTES + lane * SPLIT_BYTES,
                             (const char*)x + ((size_t)(tok0 + ci*2) * HD) * 4
                                            + lane * SPLIT_BYTES,
                             SPLIT_BYTES, mb + s * 8);
                if (++s == STAGES) { s = 0; f++; }
            }
        }
        if (lane == 0) {
            if (f >= 1) MBAR_WAIT(mb + 24 + s * 8, (f & 1) ^ 1);
            uid[s] = 0xFFFFFFFFu;
            MBAR_ARRIVE(mb + s * 8);
        }
        return;
    }

    if (warp >= CWARPS + 1) {
        // ============ LDG warps: autonomous 2-token claims, comp via smem LDS ============
        const ulonglong2* csU = (const ulonglong2*)comp_s;
        for (;;) {
            unsigned g;
            if (lane == 0) g = atomicAdd(&g_grp_ctr, 1u);
            g = __shfl_sync(0xffffffffu, g, 0);
            if (g >= NGROUP) break;
            const unsigned tok0 = g * 2;
            const ulonglong2* x0 = (const ulonglong2*)(x + (size_t)tok0 * HD);
            const ulonglong2* x1 = x0 + (HD/4);

            ulonglong2 b0[4], b1[4];
            #pragma unroll
            for (int j = 0; j < 4; j++) {
                b0[j] = __ldcs(x0 + j*32 + lane);
                b1[j] = __ldcs(x1 + j*32 + lane);
            }
            unsigned long long a0[NP], a1[NP];
            #pragma unroll
            for (int p = 0; p < NP; p++) { a0[p] = 0ull; a1[p] = 0ull; }

            #pragma unroll 4
            for (int i = 0; i < 32; i++) {
                ulonglong2 va = b0[i & 3];
                ulonglong2 vb = b1[i & 3];
                if (i + 4 < 32) {
                    b0[i & 3] = __ldcs(x0 + (i+4)*32 + lane);
                    b1[i & 3] = __ldcs(x1 + (i+4)*32 + lane);
                }
                #pragma unroll
                for (int p = 0; p < NP; p++) {
                    ulonglong2 c = csU[p * (HD/4) + i*32 + lane];
                    FMA2(a0[p], va.x, c.x); FMA2(a0[p], va.y, c.y);
                    FMA2(a1[p], vb.x, c.x); FMA2(a1[p], vb.y, c.y);
                }
            }

            #pragma unroll
            for (int t = 0; t < 2; t++) {
                unsigned long long* ac = t ? a1 : a0;
                unsigned long long u[3];
                #pragma unroll
                for (int j = 0; j < 3; j++) {
                    float f0 = __uint_as_float((unsigned)(ac[2*j]   & 0xffffffffull)) +
                               __uint_as_float((unsigned)(ac[2*j]   >> 32));
                    float f1 = __uint_as_float((unsigned)(ac[2*j+1] & 0xffffffffull)) +
                               __uint_as_float((unsigned)(ac[2*j+1] >> 32));
                    u[j] = ((unsigned long long)__float_as_uint(f1) << 32) | __float_as_uint(f0);
                }
                #pragma unroll
                for (int o = 16; o >= 1; o >>= 1)
                    #pragma unroll
                    for (int j = 0; j < 3; j++) {
                        unsigned long long v = __shfl_xor_sync(0xffffffffu, u[j], o);
                        ADD2(u[j], u[j], v);
                    }
                float pr[NP];
                #pragma unroll
                for (int j = 0; j < 3; j++) {
                    pr[2*j]   = __uint_as_float((unsigned)(u[j] & 0xffffffffull)) - mpj[2*j];
                    pr[2*j+1] = __uint_as_float((unsigned)(u[j] >> 32))           - mpj[2*j+1];
                }
                WARP_EPILOGUE(tok0 + t, pr);
            }
        }
        return;
    }

    // ============ consumers (warps 0..15): TMA ring ============
    int s = 0, f = 0;
    for (;;) {
        MBAR_WAIT(mb + s * 8, f & 1);
        unsigned u = uid[s];
        if (u == 0xFFFFFFFFu) break;
        const unsigned tokg = u >> 8;
        const int ltok = (int)((u >> 1) & 0x7Fu);
        const int last = (int)(u & 1u);

        #pragma unroll
        for (int t = 0; t < STAGE_TOK; t++) {
            const ulonglong2* xp = (const ulonglong2*)
                (smem_c + XS_OFF + s * STAGE_BYTES + t * (HD*4) + warp * (SLICE*4));
            ulonglong2 xa = xp[lane];
            ulonglong2 xb = xp[lane + 32];
            TOKEN_COMPUTE(xa, xb, ltok + t);
        }
        __syncwarp();
        if (lane == 0) MBAR_ARRIVE(mb + 24 + s * 8);
        if (++s == STAGES) { s = 0; f ^= 1; }

        if (last) {
            CBAR();
            const int ntok = ltok + 2;
            if (warp < ntok) {
                const unsigned tok = (tokg - (unsigned)ltok) + warp;
                float pr[NP];
                #pragma unroll
                for (int p = 0; p < NP; p++) {
                    float v = part[(warp*NP + p)*32 + lane];
                    #pragma unroll
                    for (int o = 16; o > 0; o >>= 1)
                        v += __shfl_xor_sync(0xffffffffu, v, o);
                    pr[p] = v - mpj[p];
                }
                WARP_EPILOGUE(tok, pr);
            }
            CBAR();
        }
    }
}

extern "C" void kernel_launch(void* const* d_in, const int* in_sizes, int n_in,
                              void* d_out, int out_size)
{
    const float* x    = (const float*)d_in[0];
    const float* mean = (const float*)d_in[1];
    const float* comp = (const float*)d_in[2];
    const float* cent = (const float*)d_in[3];
    float* out = (float*)d_out;

    reset_ctr_kernel<<<1, 1>>>();
    cudaFuncSetAttribute(kdtree_router_kernel,
                         cudaFuncAttributeMaxDynamicSharedMemorySize, SMEM_BYTES);
    kdtree_router_kernel<<<GRID, NTHREADS, SMEM_BYTES>>>(x, mean, comp, cent, out);
}

// round 16
// speedup vs baseline: 2.3087x; 1.2831x over previous
#include <cuda_runtime.h>
#include <stdint.h>
#include <math.h>

#define NTOK 16384
#define HD   4096
#define NE   64
#define NP   6
#define TK   8

#define CWARPS   16
#define NTHREADS ((CWARPS + 1) * 32)    // 544
#define PROD_WARP CWARPS
#define SLICE    (HD / CWARPS)          // 256

#define UNIT_TOK  16
#define NUNITS    (NTOK / UNIT_TOK)     // 1024
#define STAGE_TOK 2
#define STAGE_BYTES (STAGE_TOK * HD * 4)   // 32768
#define NSPLIT    4
#define SPLIT_BYTES (STAGE_BYTES / NSPLIT) // 8192
#define STAGES    4
#define CPU       (UNIT_TOK / STAGE_TOK)   // 8 chunks per unit
#define GRID      148
#define BIGCTAS   (NUNITS - GRID * (NUNITS / GRID))   // 136 CTAs take 7 units

// smem byte offsets
#define XS_OFF    0
#define PART_OFF  (STAGES * STAGE_BYTES)                 // 131072
#define PART_SZ   ((UNIT_TOK + 1) * NP * 32 * 4)         // 13056
#define CENT_OFF  (PART_OFF + PART_SZ)
#define CENTN_OFF (CENT_OFF + NE * NP * 4)
#define MBAR_OFF  ((CENTN_OFF + NE * 4 + 7) & ~7)
#define SMEM_BYTES (MBAR_OFF + 64)

#define FMA2(acc, a, b) \
    asm("fma.rn.f32x2 %0, %1, %2, %0;" : "+l"(acc) : "l"(a), "l"(b))
#define ADD2(d, a, b) \
    asm("add.rn.f32x2 %0, %1, %2;" : "=l"(d) : "l"(a), "l"(b))

__device__ __forceinline__ uint32_t smem_u32(const void* p) {
    uint32_t a;
    asm("{ .reg .u64 t; cvta.to.shared.u64 t, %1; cvt.u32.u64 %0, t; }" : "=r"(a) : "l"(p));
    return a;
}

#define MBAR_INIT(addr, cnt) \
    asm volatile("mbarrier.init.shared.b64 [%0], %1;" :: "r"(addr), "r"(cnt) : "memory")
#define MBAR_EXPECT_TX(addr, bytes) \
    asm volatile("mbarrier.arrive.expect_tx.shared.b64 _, [%0], %1;" :: "r"(addr), "r"(bytes) : "memory")
#define MBAR_ARRIVE(addr) \
    asm volatile("mbarrier.arrive.shared.b64 _, [%0];" :: "r"(addr) : "memory")
#define MBAR_WAIT(addr, parity) do {                                             \
    asm volatile("{\n\t.reg .pred P;\n"                                          \
        "W_%=:\n\tmbarrier.try_wait.parity.acquire.cta.shared::cta.b64 P, [%0], %1, 0x989680;\n" \
        "\t@P bra D_%=;\n\tbra W_%=;\nD_%=:\n\t}"                                \
        :: "r"(addr), "r"(parity) : "memory"); } while (0)

__device__ __forceinline__ void bulk_g2s(uint32_t dst, const void* src,
                                         uint32_t bytes, uint32_t mbar) {
    asm volatile(
        "cp.async.bulk.shared::cta.global.mbarrier::complete_tx::bytes "
        "[%0], [%1], %2, [%3];"
        :: "r"(dst), "l"(src), "r"(bytes), "r"(mbar) : "memory");
}

#define CBAR() asm volatile("bar.sync 1, 512;" ::: "memory")   // consumers only

// compute one token's projection partial (uses cA,cB,part,warp,lane from scope)
#define TOKEN_COMPUTE(xa, xb, LTOK) do {                                              \
    unsigned long long acc_[NP];                                                      \
    _Pragma("unroll")                                                                 \
    for (int p_ = 0; p_ < NP; p_++) {                                                 \
        acc_[p_] = 0ull;                                                              \
        FMA2(acc_[p_], (xa).x, cA[p_].x); FMA2(acc_[p_], (xa).y, cA[p_].y);           \
        FMA2(acc_[p_], (xb).x, cB[p_].x); FMA2(acc_[p_], (xb).y, cB[p_].y);           \
    }                                                                                 \
    unsigned long long u_[3];                                                         \
    _Pragma("unroll")                                                                 \
    for (int j_ = 0; j_ < 3; j_++) {                                                  \
        float f0_ = __uint_as_float((unsigned)(acc_[2*j_]   & 0xffffffffull)) +       \
                    __uint_as_float((unsigned)(acc_[2*j_]   >> 32));                  \
        float f1_ = __uint_as_float((unsigned)(acc_[2*j_+1] & 0xffffffffull)) +       \
                    __uint_as_float((unsigned)(acc_[2*j_+1] >> 32));                  \
        u_[j_] = ((unsigned long long)__float_as_uint(f1_) << 32) | __float_as_uint(f0_); \
    }                                                                                 \
    _Pragma("unroll")                                                                 \
    for (int o_ = 16; o_ >= 2; o_ >>= 1)                                              \
        _Pragma("unroll")                                                             \
        for (int j_ = 0; j_ < 3; j_++) {                                              \
            unsigned long long v_ = __shfl_xor_sync(0xffffffffu, u_[j_], o_);         \
            ADD2(u_[j_], u_[j_], v_);                                                 \
        }                                                                             \
    if (lane < 2) {                                                                   \
        int slot_ = warp * 2 + lane;                                                  \
        _Pragma("unroll")                                                             \
        for (int j_ = 0; j_ < 3; j_++) {                                              \
            part[((LTOK)*NP + 2*j_  )*32 + slot_] = __uint_as_float((unsigned)(u_[j_] & 0xffffffffull)); \
            part[((LTOK)*NP + 2*j_+1)*32 + slot_] = __uint_as_float((unsigned)(u_[j_] >> 32));           \
        }                                                                             \
    }                                                                                 \
} while (0)

__global__ void __launch_bounds__(NTHREADS, 1)
kdtree_router_kernel(const float* __restrict__ x,
                     const float* __restrict__ mean,
                     const float* __restrict__ comp,
                     const float* __restrict__ cent,
                     float* __restrict__ out)
{
    extern __shared__ __align__(1024) char smem_c[];
    float* part    = (float*)(smem_c + PART_OFF);
    float* cent_s  = (float*)(smem_c + CENT_OFF);
    float* centn_s = (float*)(smem_c + CENTN_OFF);
    const uint32_t mb = smem_u32(smem_c + MBAR_OFF);
    const uint32_t xs = smem_u32(smem_c + XS_OFF);

    const int tid  = threadIdx.x;
    const int lane = tid & 31;
    const int warp = tid >> 5;
    const int bid  = blockIdx.x;
    const int nb   = (bid < BIGCTAS) ? (NUNITS / GRID + 1) : (NUNITS / GRID);  // 7 or 6
    const int nchunks = nb * CPU;

    if (tid == 0) {
        #pragma unroll
        for (int s = 0; s < STAGES; s++) {
            MBAR_INIT(mb + s * 8, 1);               // full: expect_tx arrive
            MBAR_INIT(mb + 32 + s * 8, CWARPS);     // empty: 16 warp arrivals
        }
    }
    __syncthreads();   // ONLY CTA-wide barrier; producer free-runs from here

    if (warp == PROD_WARP) {
        // ======== producer: static schedule, 4 lanes x 8 KB concurrent copies ========
        unsigned pc = 0;
        #pragma unroll 1
        for (int k = 0; k < nb; k++) {
            const char* ubase = (const char*)x
                + ((size_t)(bid + GRID * k) * UNIT_TOK * HD) * 4;
            #pragma unroll 1
            for (int ci = 0; ci < CPU; ci++) {
                int s = (int)(pc & (STAGES - 1));
                unsigned up = pc >> 2;
                if (lane < NSPLIT && pc >= STAGES)
                    MBAR_WAIT(mb + 32 + s * 8, (up & 1) ^ 1);
                __syncwarp();
                if (lane == 0)
                    MBAR_EXPECT_TX(mb + s * 8, (uint32_t)STAGE_BYTES);
                __syncwarp();
                if (lane < NSPLIT)
                    bulk_g2s(xs + s * STAGE_BYTES + lane * SPLIT_BYTES,
                             ubase + (size_t)ci * STAGE_BYTES + lane * SPLIT_BYTES,
                             SPLIT_BYTES, mb + s * 8);
                pc++;
            }
        }
        return;
    }

    // ======================= consumers (warps 0..15) =======================
    for (int i = tid; i < NE * NP; i += 512) cent_s[i] = cent[i];
    CBAR();

    ulonglong2 cA[NP], cB[NP];
    {
        const ulonglong2* cp0 = (const ulonglong2*)(comp + warp * SLICE);
        #pragma unroll
        for (int p = 0; p < NP; p++) {
            cA[p] = __ldg(cp0 + (size_t)p * (HD/4) + lane);
            cB[p] = __ldg(cp0 + (size_t)p * (HD/4) + lane + 32);
        }
        const ulonglong2* mp = (const ulonglong2*)(mean + warp * SLICE);
        ulonglong2 ma = __ldg(mp + lane), mbv = __ldg(mp + lane + 32);
        TOKEN_COMPUTE(ma, mbv, UNIT_TOK);   // mean projection partials -> row 16
        if (tid < NE) {
            float s = 0.f;
            #pragma unroll
            for (int p = 0; p < NP; p++) { float c = cent_s[tid*NP + p]; s += c * c; }
            centn_s[tid] = s;
        }
    }
    CBAR();

    float mpj[NP];
    #pragma unroll
    for (int p = 0; p < NP; p++) {
        float v = part[(UNIT_TOK*NP + p)*32 + lane];
        #pragma unroll
        for (int o = 16; o > 0; o >>= 1)
            v += __shfl_xor_sync(0xffffffffu, v, o);
        mpj[p] = v;
    }

    float* out_idx = out;
    float* out_tp  = out + (size_t)NTOK * TK;
    float* out_pr  = out + 2 * (size_t)NTOK * TK;

    #pragma unroll 1
    for (unsigned pc = 0; pc < (unsigned)nchunks; pc++) {
        int s = (int)(pc & (STAGES - 1));
        unsigned up = pc >> 2;
        MBAR_WAIT(mb + s * 8, up & 1);

        const int ltok = (int)(pc & (CPU - 1)) * STAGE_TOK;     // 0,2,..,14

        #pragma unroll
        for (int t = 0; t < STAGE_TOK; t++) {
            const ulonglong2* xp = (const ulonglong2*)
                (smem_c + XS_OFF + s * STAGE_BYTES + t * (HD*4) + warp * (SLICE*4));
            ulonglong2 xa = xp[lane];
            ulonglong2 xb = xp[lane + 32];
            TOKEN_COMPUTE(xa, xb, ltok + t);
        }
        __syncwarp();
        if (lane == 0) MBAR_ARRIVE(mb + 32 + s * 8);

        if (ltok == UNIT_TOK - STAGE_TOK) {
            // ---- unit complete -> epilogue: warp w handles token w ----
            CBAR();
            const unsigned unit = bid + GRID * (pc / CPU);
            const unsigned tok  = unit * UNIT_TOK + warp;

            float pr[NP];
            #pragma unroll
            for (int p = 0; p < NP; p++) {
                float v = part[(warp*NP + p)*32 + lane];
                #pragma unroll
                for (int o = 16; o > 0; o >>= 1)
                    v += __shfl_xor_sync(0xffffffffu, v, o);
                pr[p] = v - mpj[p];
            }
            float pn = 0.f;
            #pragma unroll
            for (int p = 0; p < NP; p++) pn += pr[p] * pr[p];

            const int e0 = lane, e1 = lane + 32;
            float dot0 = 0.f, dot1 = 0.f;
            #pragma unroll
            for (int p = 0; p < NP; p++) {
                dot0 += pr[p] * cent_s[e0*NP + p];
                dot1 += pr[p] * cent_s[e1*NP + p];
            }
            float d20 = pn - 2.f*dot0 + centn_s[e0];
            float d21 = pn - 2.f*dot1 + centn_s[e1];
            float s0 = -sqrtf(fmaxf(d20, 0.f));
            float s1 = -sqrtf(fmaxf(d21, 0.f));

            float m = fmaxf(s0, s1);
            #pragma unroll
            for (int o = 16; o > 0; o >>= 1)
                m = fmaxf(m, __shfl_xor_sync(0xffffffffu, m, o));
            float ex0 = expf(s0 - m);
            float ex1 = expf(s1 - m);
            float sum = ex0 + ex1;
            #pragma unroll
            for (int o = 16; o > 0; o >>= 1)
                sum += __shfl_xor_sync(0xffffffffu, sum, o);
            float p0 = ex0 / sum;
            float p1 = ex1 / sum;

            out_pr[(size_t)tok*NE + e0] = p0;
            out_pr[(size_t)tok*NE + e1] = p1;

            // top-8 via 8-round warp argmax; tie-break = lower index (jax.lax.top_k)
            unsigned long long k0 = ((unsigned long long)__float_as_uint(p0) << 32) | (unsigned)(NE-1 - e0);
            unsigned long long k1 = ((unsigned long long)__float_as_uint(p1) << 32) | (unsigned)(NE-1 - e1);
            float tsum = 0.f, myp = 0.f;
            int myi = 0;
            #pragma unroll
            for (int r = 0; r < TK; r++) {
                unsigned long long b = (k0 > k1) ? k0 : k1;
                #pragma unroll
                for (int o = 16; o > 0; o >>= 1) {
                    unsigned long long v = __shfl_xor_sync(0xffffffffu, b, o);
                    if (v > b) b = v;
                }
                int idx = NE-1 - (int)(b & 0xffull);
                float pv = __uint_as_float((unsigned)(b >> 32));
                tsum += pv;
                if (lane == r) { myp = pv; myi = idx; }
                if (idx == e0) k0 = 0ull;
                if (idx == e1) k1 = 0ull;
            }
            if (lane < TK) {
                out_idx[(size_t)tok*TK + lane] = (float)myi;
                out_tp [(size_t)tok*TK + lane] = myp / tsum;
            }
            CBAR();   // protect part[] before next unit overwrites
        }
    }
}

extern "C" void kernel_launch(void* const* d_in, const int* in_sizes, int n_in,
                              void* d_out, int out_size)
{
    const float* x    = (const float*)d_in[0];
    const float* mean = (const float*)d_in[1];
    const float* comp = (const float*)d_in[2];
    const float* cent = (const float*)d_in[3];
    float* out = (float*)d_out;

    cudaFuncSetAttribute(kdtree_router_kernel,
                         cudaFuncAttributeMaxDynamicSharedMemorySize, SMEM_BYTES);
    kdtree_router_kernel<<<GRID, NTHREADS, SMEM_BYTES>>>(x, mean, comp, cent, out);
}